// round 6
// baseline (speedup 1.0000x reference)
#include <cuda_runtime.h>

#define BB   1024
#define FF   39
#define KK   16
#define PP   741
#define PPP  768                      // padded L2 row stride
#define TT   9139
#define TTP  9216                     // padded L3 row stride (36*256)
#define ROWP 20                       // padded embedding row stride (floats)
#define NTHR 256
#define BSPLIT 8                      // batch split for stats kernels
#define TSPLIT 4                      // T split for final reduce
#define TCHUNK (TTP / TSPLIT)         // 2304

// ---- device-global scratch (no allocations allowed) ----
__device__ __align__(16) float g_L2[BB * PPP];          // ~3.1 MB
__device__ __align__(16) float g_L3[(size_t)BB * TTP];  // ~37.7 MB
__device__ float g_lin[BB];
__device__ __align__(16) float g_c2[PPP];   // padding stays 0 (never written)
__device__ __align__(16) float g_c3[TTP];   // padding stays 0 (never written)
__device__ float g_s2[PPP], g_q2[PPP];
__device__ float g_s3[TTP], g_q3[TTP];
__device__ __align__(16) int g_tri[TTP];    // pair_idx | (c<<16); padding stays 0
__device__ float g_sumo;
__device__ float g_facc[BB];

// ---------------------------------------------------------------------------
// Kernel 0: pack triple -> (pair idx, third elem); zero all accumulators
// grid covers TTP
// ---------------------------------------------------------------------------
__global__ void pack_tri(const int* __restrict__ i1, const int* __restrict__ i2,
                         const int* __restrict__ i3) {
    int t = blockIdx.x * blockDim.x + threadIdx.x;
    if (t < TT) {
        int a = i1[t], b2 = i2[t], c = i3[t];
        int p = a * (FF - 1) - (a * (a - 1)) / 2 + (b2 - a - 1);
        g_tri[t] = p | (c << 16);
    }
    if (t < TTP) { g_s3[t] = 0.f; g_q3[t] = 0.f; }
    if (t < PPP) { g_s2[t] = 0.f; g_q2[t] = 0.f; }
    if (t < BB)  g_facc[t] = 0.f;
    if (t == 0)  g_sumo = 0.f;
}

// ---------------------------------------------------------------------------
// Kernel A: per-batch-row gather + pair products + level2 + level3
// ---------------------------------------------------------------------------
__global__ __launch_bounds__(NTHR) void compute_levels(
    const int*   __restrict__ feats,
    const float* __restrict__ w,
    const float* __restrict__ v,
    const int*   __restrict__ rows,
    const int*   __restrict__ cols)
{
    extern __shared__ float dsm[];
    float* P2  = dsm;                // 741*16 floats
    float* sxv = dsm + PP * KK;      // 39*20 floats
    __shared__ int sidx[FF];

    const int b   = blockIdx.x;
    const int tid = threadIdx.x;

    if (tid < FF) sidx[tid] = feats[b * FF + tid];
    __syncthreads();

    for (int e = tid; e < FF * KK; e += NTHR) {
        int f = e >> 4, k = e & 15;
        sxv[f * ROWP + k] = v[(size_t)sidx[f] * KK + k];
    }
    if (tid < 32) {
        float s = 0.f;
        for (int f = tid; f < FF; f += 32) s += w[sidx[f]];
        #pragma unroll
        for (int o = 16; o; o >>= 1) s += __shfl_down_sync(0xffffffffu, s, o);
        if (tid == 0) g_lin[b] = s;
    }
    __syncthreads();

    // ---- Phase A: pair products + level2 ----
    for (int p = tid; p < PP; p += NTHR) {
        int r = rows[p], c = cols[p];
        const float4* er = (const float4*)&sxv[r * ROWP];
        const float4* ec = (const float4*)&sxv[c * ROWP];
        float4* Pq = (float4*)&P2[p * KK];
        float s2 = 0.f;
        #pragma unroll
        for (int q = 0; q < 4; q++) {
            float4 a4 = er[q], b4 = ec[q], m;
            m.x = a4.x * b4.x; m.y = a4.y * b4.y;
            m.z = a4.z * b4.z; m.w = a4.w * b4.w;
            Pq[q] = m;
            s2 += m.x + m.y + m.z + m.w;
        }
        g_L2[b * PPP + p] = s2;
    }
    __syncthreads();

    // ---- Phase B: 4 triples per thread, guard-free over TTP (9 iterations) ----
    float* dst = g_L3 + (size_t)b * TTP;
    for (int t = tid * 4; t < TTP; t += NTHR * 4) {
        int4 d4 = *(const int4*)&g_tri[t];
        float4 r4;
        {
            const float4* Pp = (const float4*)&P2[(d4.x & 0xFFFF) * KK];
            const float4* Ec = (const float4*)&sxv[(d4.x >> 16) * ROWP];
            float s = 0.f;
            #pragma unroll
            for (int q = 0; q < 4; q++) { float4 a = Pp[q], e = Ec[q];
                s += a.x*e.x + a.y*e.y + a.z*e.z + a.w*e.w; }
            r4.x = s;
        }
        {
            const float4* Pp = (const float4*)&P2[(d4.y & 0xFFFF) * KK];
            const float4* Ec = (const float4*)&sxv[(d4.y >> 16) * ROWP];
            float s = 0.f;
            #pragma unroll
            for (int q = 0; q < 4; q++) { float4 a = Pp[q], e = Ec[q];
                s += a.x*e.x + a.y*e.y + a.z*e.z + a.w*e.w; }
            r4.y = s;
        }
        {
            const float4* Pp = (const float4*)&P2[(d4.z & 0xFFFF) * KK];
            const float4* Ec = (const float4*)&sxv[(d4.z >> 16) * ROWP];
            float s = 0.f;
            #pragma unroll
            for (int q = 0; q < 4; q++) { float4 a = Pp[q], e = Ec[q];
                s += a.x*e.x + a.y*e.y + a.z*e.z + a.w*e.w; }
            r4.z = s;
        }
        {
            const float4* Pp = (const float4*)&P2[(d4.w & 0xFFFF) * KK];
            const float4* Ec = (const float4*)&sxv[(d4.w >> 16) * ROWP];
            float s = 0.f;
            #pragma unroll
            for (int q = 0; q < 4; q++) { float4 a = Pp[q], e = Ec[q];
                s += a.x*e.x + a.y*e.y + a.z*e.z + a.w*e.w; }
            r4.w = s;
        }
        *(float4*)&dst[t] = r4;
    }
}

// ---------------------------------------------------------------------------
// Kernel B: batch-split column stats; partials via RED into g_s/g_q
// CTA = 32 tx * 8 ty; tx owns 4 consecutive columns; 128 b-rows per CTA
// ---------------------------------------------------------------------------
__global__ __launch_bounds__(NTHR) void stats3_acc()
{
    __shared__ float4 ss[NTHR], sq[NTHR];
    const int tx = threadIdx.x & 31;
    const int ty = threadIdx.x >> 5;
    const int t0 = blockIdx.x * 128 + tx * 4;
    const int b0 = blockIdx.y * (BB / BSPLIT);

    float4 s = make_float4(0.f, 0.f, 0.f, 0.f);
    float4 q = make_float4(0.f, 0.f, 0.f, 0.f);
    #pragma unroll 8
    for (int i = ty; i < BB / BSPLIT; i += 8) {
        float4 x = *(const float4*)(g_L3 + (size_t)(b0 + i) * TTP + t0);
        s.x += x.x; s.y += x.y; s.z += x.z; s.w += x.w;
        q.x += x.x * x.x; q.y += x.y * x.y; q.z += x.z * x.z; q.w += x.w * x.w;
    }
    ss[threadIdx.x] = s; sq[threadIdx.x] = q;
    __syncthreads();
    if (ty == 0) {
        #pragma unroll
        for (int j = 1; j < 8; j++) {
            float4 a = ss[j * 32 + tx], c4 = sq[j * 32 + tx];
            s.x += a.x; s.y += a.y; s.z += a.z; s.w += a.w;
            q.x += c4.x; q.y += c4.y; q.z += c4.z; q.w += c4.w;
        }
        atomicAdd(&g_s3[t0 + 0], s.x); atomicAdd(&g_q3[t0 + 0], q.x);
        atomicAdd(&g_s3[t0 + 1], s.y); atomicAdd(&g_q3[t0 + 1], q.y);
        atomicAdd(&g_s3[t0 + 2], s.z); atomicAdd(&g_q3[t0 + 2], q.z);
        atomicAdd(&g_s3[t0 + 3], s.w); atomicAdd(&g_q3[t0 + 3], q.w);
    }
}

__global__ __launch_bounds__(NTHR) void stats2_acc()
{
    __shared__ float4 ss[NTHR], sq[NTHR];
    const int tx = threadIdx.x & 31;
    const int ty = threadIdx.x >> 5;
    const int p0 = blockIdx.x * 128 + tx * 4;
    const int b0 = blockIdx.y * (BB / BSPLIT);

    float4 s = make_float4(0.f, 0.f, 0.f, 0.f);
    float4 q = make_float4(0.f, 0.f, 0.f, 0.f);
    #pragma unroll 8
    for (int i = ty; i < BB / BSPLIT; i += 8) {
        float4 x = *(const float4*)(g_L2 + (b0 + i) * PPP + p0);
        s.x += x.x; s.y += x.y; s.z += x.z; s.w += x.w;
        q.x += x.x * x.x; q.y += x.y * x.y; q.z += x.z * x.z; q.w += x.w * x.w;
    }
    ss[threadIdx.x] = s; sq[threadIdx.x] = q;
    __syncthreads();
    if (ty == 0) {
        #pragma unroll
        for (int j = 1; j < 8; j++) {
            float4 a = ss[j * 32 + tx], c4 = sq[j * 32 + tx];
            s.x += a.x; s.y += a.y; s.z += a.z; s.w += a.w;
            q.x += c4.x; q.y += c4.y; q.z += c4.z; q.w += c4.w;
        }
        atomicAdd(&g_s2[p0 + 0], s.x); atomicAdd(&g_q2[p0 + 0], q.x);
        atomicAdd(&g_s2[p0 + 1], s.y); atomicAdd(&g_q2[p0 + 1], q.y);
        atomicAdd(&g_s2[p0 + 2], s.z); atomicAdd(&g_q2[p0 + 2], q.z);
        atomicAdd(&g_s2[p0 + 3], s.w); atomicAdd(&g_q2[p0 + 3], q.w);
    }
}

// ---------------------------------------------------------------------------
// Kernel C: sums -> affine coefficients c; accumulate Sum(o) into g_sumo
// ---------------------------------------------------------------------------
__global__ __launch_bounds__(NTHR) void finalize(
    const float* __restrict__ gamma2, const float* __restrict__ beta2,
    const float* __restrict__ gw2,
    const float* __restrict__ gamma3, const float* __restrict__ beta3,
    const float* __restrict__ gw3)
{
    const int i = blockIdx.x * NTHR + threadIdx.x;
    float osum = 0.f;
    if (i < TT) {
        float mean = g_s3[i] * (1.0f / BB);
        float var  = g_q3[i] * (1.0f / BB) - mean * mean;
        float inv  = rsqrtf(var + 1e-3f);
        float cc   = gamma3[i] * gw3[i] * inv;
        g_c3[i] = cc;
        osum += beta3[i] * gw3[i] - cc * mean;
    }
    if (i < PP) {
        float mean = g_s2[i] * (1.0f / BB);
        float var  = g_q2[i] * (1.0f / BB) - mean * mean;
        float inv  = rsqrtf(var + 1e-3f);
        float cc   = gamma2[i] * gw2[i] * inv;
        g_c2[i] = cc;
        osum += beta2[i] * gw2[i] - cc * mean;
    }
    #pragma unroll
    for (int o = 16; o; o >>= 1) osum += __shfl_down_sync(0xffffffffu, osum, o);
    __shared__ float red[8];
    if ((threadIdx.x & 31) == 0) red[threadIdx.x >> 5] = osum;
    __syncthreads();
    if (threadIdx.x == 0) {
        float s = 0.f;
        #pragma unroll
        for (int j = 0; j < 8; j++) s += red[j];
        atomicAdd(&g_sumo, s);
    }
}

// ---------------------------------------------------------------------------
// Kernel D: weighted reductions. 8 b-rows per CTA, T split 4-way (grid.y).
// Padding columns carry c3=0 so the loop is guard-free and fully float4.
// ---------------------------------------------------------------------------
__global__ __launch_bounds__(NTHR) void final_reduce()
{
    const int b0  = blockIdx.x * 8;
    const int tid = threadIdx.x;
    const int tlo = blockIdx.y * TCHUNK;
    const int thi = tlo + TCHUNK;
    float acc[8] = {0.f, 0.f, 0.f, 0.f, 0.f, 0.f, 0.f, 0.f};

    for (int t = tlo + tid * 4; t < thi; t += NTHR * 4) {
        float4 c = *(const float4*)&g_c3[t];
        const float* base = g_L3 + (size_t)b0 * TTP + t;
        #pragma unroll
        for (int j = 0; j < 8; j++) {
            float4 x = *(const float4*)(base + (size_t)j * TTP);
            acc[j] += c.x * x.x + c.y * x.y + c.z * x.z + c.w * x.w;
        }
    }
    if (blockIdx.y == 0) {
        for (int p = tid * 4; p < PPP; p += NTHR * 4) {
            float4 c = *(const float4*)&g_c2[p];
            const float* base = g_L2 + b0 * PPP + p;
            #pragma unroll
            for (int j = 0; j < 8; j++) {
                float4 x = *(const float4*)(base + j * PPP);
                acc[j] += c.x * x.x + c.y * x.y + c.z * x.z + c.w * x.w;
            }
        }
    }

    __shared__ float red[8][8];   // [warp][j]
    #pragma unroll
    for (int j = 0; j < 8; j++) {
        float vsum = acc[j];
        #pragma unroll
        for (int o = 16; o; o >>= 1) vsum += __shfl_down_sync(0xffffffffu, vsum, o);
        if ((tid & 31) == 0) red[tid >> 5][j] = vsum;
    }
    __syncthreads();
    if (tid < 8) {
        float s = 0.f;
        #pragma unroll
        for (int wp = 0; wp < 8; wp++) s += red[wp][tid];
        atomicAdd(&g_facc[b0 + tid], s);
    }
}

// ---------------------------------------------------------------------------
// Kernel E: epilogue -> logits
// ---------------------------------------------------------------------------
__global__ void epilogue(const float* __restrict__ bias, float* __restrict__ out)
{
    int b = blockIdx.x * blockDim.x + threadIdx.x;
    if (b < BB) out[b] = g_facc[b] + g_lin[b] + bias[0] + g_sumo;
}

// ---------------------------------------------------------------------------
extern "C" void kernel_launch(void* const* d_in, const int* in_sizes, int n_in,
                              void* d_out, int out_size)
{
    const int*   feats  = (const int*)  d_in[0];
    const float* w      = (const float*)d_in[1];
    const float* v      = (const float*)d_in[2];
    const float* bias   = (const float*)d_in[3];
    const float* gamma2 = (const float*)d_in[4];
    const float* beta2  = (const float*)d_in[5];
    const float* gw2    = (const float*)d_in[6];
    const float* gamma3 = (const float*)d_in[7];
    const float* beta3  = (const float*)d_in[8];
    const float* gw3    = (const float*)d_in[9];
    const int*   rows   = (const int*)  d_in[10];
    const int*   cols   = (const int*)  d_in[11];
    const int*   i1     = (const int*)  d_in[12];
    const int*   i2     = (const int*)  d_in[13];
    const int*   i3     = (const int*)  d_in[14];
    float* out = (float*)d_out;

    const int dyn_smem = (PP * KK + FF * ROWP) * (int)sizeof(float);  // ~50.5 KB
    cudaFuncSetAttribute(compute_levels,
                         cudaFuncAttributeMaxDynamicSharedMemorySize, dyn_smem);

    pack_tri<<<TTP / NTHR, NTHR>>>(i1, i2, i3);
    compute_levels<<<BB, NTHR, dyn_smem>>>(feats, w, v, rows, cols);
    stats2_acc<<<dim3(PPP / 128, BSPLIT), NTHR>>>();
    stats3_acc<<<dim3(TTP / 128, BSPLIT), NTHR>>>();
    finalize<<<TTP / NTHR, NTHR>>>(gamma2, beta2, gw2, gamma3, beta3, gw3);
    final_reduce<<<dim3(BB / 8, TSPLIT), NTHR>>>();
    epilogue<<<BB / NTHR, NTHR>>>(bias, out);
}

// round 7
// speedup vs baseline: 1.2711x; 1.2711x over previous
#include <cuda_runtime.h>

#define BB   1024
#define FF   39
#define KK   16
#define PP   741
#define PPP  768                      // padded L2 row stride
#define TT   9139
#define TTP  9216                     // padded L3 row stride
#define SP   20                       // P2 row stride (floats): conflict-free LDS.128
#define SE   20                       // embedding row stride (floats)
#define NTHR 256
#define BSPLIT 16                     // batch split for stats kernels
#define TSPLIT 8                      // T split for final reduce
#define TCHUNK (TTP / TSPLIT)         // 1152

// ---- device-global scratch (no allocations allowed) ----
__device__ __align__(16) float g_L2[BB * PPP];          // ~3.1 MB
__device__ __align__(16) float g_L3[(size_t)BB * TTP];  // ~37.7 MB
__device__ float g_lin[BB];
__device__ __align__(16) float g_c2[PPP];   // padding stays 0 (never written)
__device__ __align__(16) float g_c3[TTP];   // padding stays 0 (never written)
__device__ float g_s2[PPP], g_q2[PPP];
__device__ float g_s3[TTP], g_q3[TTP];
__device__ __align__(16) int g_tri[TTP];    // pair_idx | (c<<16); padding stays 0
__device__ float g_sumo;
__device__ float g_facc[BB];

// ---------------------------------------------------------------------------
// Kernel 0: pack triple -> (pair idx, third elem); zero all accumulators
// ---------------------------------------------------------------------------
__global__ void pack_tri(const int* __restrict__ i1, const int* __restrict__ i2,
                         const int* __restrict__ i3) {
    int t = blockIdx.x * blockDim.x + threadIdx.x;
    if (t < TT) {
        int a = i1[t], b2 = i2[t], c = i3[t];
        int p = a * (FF - 1) - (a * (a - 1)) / 2 + (b2 - a - 1);
        g_tri[t] = p | (c << 16);
    }
    if (t < TTP) { g_s3[t] = 0.f; g_q3[t] = 0.f; }
    if (t < PPP) { g_s2[t] = 0.f; g_q2[t] = 0.f; }
    if (t < BB)  g_facc[t] = 0.f;
    if (t == 0)  g_sumo = 0.f;
}

// ---------------------------------------------------------------------------
// Kernel A: per-batch-row gather + pair products + level2 + level3
// Phase B: ONE TRIPLE PER LANE (stride-1) + stride-20 rows -> conflict-free
//          LDS.128 (each 8-lane phase of consecutive c tiles all 32 banks)
// ---------------------------------------------------------------------------
__global__ __launch_bounds__(NTHR) void compute_levels(
    const int*   __restrict__ feats,
    const float* __restrict__ w,
    const float* __restrict__ v,
    const int*   __restrict__ rows,
    const int*   __restrict__ cols)
{
    extern __shared__ float dsm[];
    float* P2  = dsm;                // 741*20 floats (59.3 KB)
    float* sxv = dsm + PP * SP;      // 39*20 floats
    __shared__ int sidx[FF];

    const int b   = blockIdx.x;
    const int tid = threadIdx.x;

    if (tid < FF) sidx[tid] = feats[b * FF + tid];
    __syncthreads();

    for (int e = tid; e < FF * KK; e += NTHR) {
        int f = e >> 4, k = e & 15;
        sxv[f * SE + k] = v[(size_t)sidx[f] * KK + k];
    }
    if (tid < 32) {
        float s = 0.f;
        for (int f = tid; f < FF; f += 32) s += w[sidx[f]];
        #pragma unroll
        for (int o = 16; o; o >>= 1) s += __shfl_down_sync(0xffffffffu, s, o);
        if (tid == 0) g_lin[b] = s;
    }
    __syncthreads();

    // ---- Phase A: pair products + level2 (consecutive p per lane:
    //      r consecutive, c broadcast -> conflict-free) ----
    for (int p = tid; p < PP; p += NTHR) {
        int r = rows[p], c = cols[p];
        const float4* er = (const float4*)&sxv[r * SE];
        const float4* ec = (const float4*)&sxv[c * SE];
        float4* Pq = (float4*)&P2[p * SP];
        float s2 = 0.f;
        #pragma unroll
        for (int q = 0; q < 4; q++) {
            float4 a4 = er[q], b4 = ec[q], m;
            m.x = a4.x * b4.x; m.y = a4.y * b4.y;
            m.z = a4.z * b4.z; m.w = a4.w * b4.w;
            Pq[q] = m;
            s2 += m.x + m.y + m.z + m.w;
        }
        g_L2[b * PPP + p] = s2;
    }
    __syncthreads();

    // ---- Phase B: guard-free over TTP, one triple per lane ----
    float* dst = g_L3 + (size_t)b * TTP;
    for (int t = tid; t < TTP; t += NTHR) {
        int d = __ldg(&g_tri[t]);
        const float4* Pp = (const float4*)&P2[(d & 0xFFFF) * SP];
        const float4* Ec = (const float4*)&sxv[(d >> 16) * SE];
        float s = 0.f;
        #pragma unroll
        for (int q = 0; q < 4; q++) {
            float4 a = Pp[q], e = Ec[q];
            s += a.x * e.x + a.y * e.y + a.z * e.z + a.w * e.w;
        }
        dst[t] = s;
    }
}

// ---------------------------------------------------------------------------
// Kernel B: batch-split column stats; partials via RED into g_s/g_q
// ---------------------------------------------------------------------------
__global__ __launch_bounds__(NTHR) void stats3_acc()
{
    __shared__ float4 ss[NTHR], sq[NTHR];
    const int tx = threadIdx.x & 31;
    const int ty = threadIdx.x >> 5;
    const int t0 = blockIdx.x * 128 + tx * 4;
    const int b0 = blockIdx.y * (BB / BSPLIT);

    float4 s = make_float4(0.f, 0.f, 0.f, 0.f);
    float4 q = make_float4(0.f, 0.f, 0.f, 0.f);
    #pragma unroll 8
    for (int i = ty; i < BB / BSPLIT; i += 8) {
        float4 x = *(const float4*)(g_L3 + (size_t)(b0 + i) * TTP + t0);
        s.x += x.x; s.y += x.y; s.z += x.z; s.w += x.w;
        q.x += x.x * x.x; q.y += x.y * x.y; q.z += x.z * x.z; q.w += x.w * x.w;
    }
    ss[threadIdx.x] = s; sq[threadIdx.x] = q;
    __syncthreads();
    if (ty == 0) {
        #pragma unroll
        for (int j = 1; j < 8; j++) {
            float4 a = ss[j * 32 + tx], c4 = sq[j * 32 + tx];
            s.x += a.x; s.y += a.y; s.z += a.z; s.w += a.w;
            q.x += c4.x; q.y += c4.y; q.z += c4.z; q.w += c4.w;
        }
        atomicAdd(&g_s3[t0 + 0], s.x); atomicAdd(&g_q3[t0 + 0], q.x);
        atomicAdd(&g_s3[t0 + 1], s.y); atomicAdd(&g_q3[t0 + 1], q.y);
        atomicAdd(&g_s3[t0 + 2], s.z); atomicAdd(&g_q3[t0 + 2], q.z);
        atomicAdd(&g_s3[t0 + 3], s.w); atomicAdd(&g_q3[t0 + 3], q.w);
    }
}

__global__ __launch_bounds__(NTHR) void stats2_acc()
{
    __shared__ float4 ss[NTHR], sq[NTHR];
    const int tx = threadIdx.x & 31;
    const int ty = threadIdx.x >> 5;
    const int p0 = blockIdx.x * 128 + tx * 4;
    const int b0 = blockIdx.y * (BB / BSPLIT);

    float4 s = make_float4(0.f, 0.f, 0.f, 0.f);
    float4 q = make_float4(0.f, 0.f, 0.f, 0.f);
    #pragma unroll 8
    for (int i = ty; i < BB / BSPLIT; i += 8) {
        float4 x = *(const float4*)(g_L2 + (b0 + i) * PPP + p0);
        s.x += x.x; s.y += x.y; s.z += x.z; s.w += x.w;
        q.x += x.x * x.x; q.y += x.y * x.y; q.z += x.z * x.z; q.w += x.w * x.w;
    }
    ss[threadIdx.x] = s; sq[threadIdx.x] = q;
    __syncthreads();
    if (ty == 0) {
        #pragma unroll
        for (int j = 1; j < 8; j++) {
            float4 a = ss[j * 32 + tx], c4 = sq[j * 32 + tx];
            s.x += a.x; s.y += a.y; s.z += a.z; s.w += a.w;
            q.x += c4.x; q.y += c4.y; q.z += c4.z; q.w += c4.w;
        }
        atomicAdd(&g_s2[p0 + 0], s.x); atomicAdd(&g_q2[p0 + 0], q.x);
        atomicAdd(&g_s2[p0 + 1], s.y); atomicAdd(&g_q2[p0 + 1], q.y);
        atomicAdd(&g_s2[p0 + 2], s.z); atomicAdd(&g_q2[p0 + 2], q.z);
        atomicAdd(&g_s2[p0 + 3], s.w); atomicAdd(&g_q2[p0 + 3], q.w);
    }
}

// ---------------------------------------------------------------------------
// Kernel C: sums -> affine coefficients c; accumulate Sum(o) into g_sumo
// ---------------------------------------------------------------------------
__global__ __launch_bounds__(NTHR) void finalize(
    const float* __restrict__ gamma2, const float* __restrict__ beta2,
    const float* __restrict__ gw2,
    const float* __restrict__ gamma3, const float* __restrict__ beta3,
    const float* __restrict__ gw3)
{
    const int i = blockIdx.x * NTHR + threadIdx.x;
    float osum = 0.f;
    if (i < TT) {
        float mean = g_s3[i] * (1.0f / BB);
        float var  = g_q3[i] * (1.0f / BB) - mean * mean;
        float inv  = rsqrtf(var + 1e-3f);
        float cc   = gamma3[i] * gw3[i] * inv;
        g_c3[i] = cc;
        osum += beta3[i] * gw3[i] - cc * mean;
    }
    if (i < PP) {
        float mean = g_s2[i] * (1.0f / BB);
        float var  = g_q2[i] * (1.0f / BB) - mean * mean;
        float inv  = rsqrtf(var + 1e-3f);
        float cc   = gamma2[i] * gw2[i] * inv;
        g_c2[i] = cc;
        osum += beta2[i] * gw2[i] - cc * mean;
    }
    #pragma unroll
    for (int o = 16; o; o >>= 1) osum += __shfl_down_sync(0xffffffffu, osum, o);
    __shared__ float red[8];
    if ((threadIdx.x & 31) == 0) red[threadIdx.x >> 5] = osum;
    __syncthreads();
    if (threadIdx.x == 0) {
        float s = 0.f;
        #pragma unroll
        for (int j = 0; j < 8; j++) s += red[j];
        atomicAdd(&g_sumo, s);
    }
}

// ---------------------------------------------------------------------------
// Kernel D: weighted reductions. 8 b-rows per CTA, T split 8-way (grid.y).
// Padding columns carry c3=0 so the loop is guard-free and fully float4.
// ---------------------------------------------------------------------------
__global__ __launch_bounds__(NTHR) void final_reduce()
{
    const int b0  = blockIdx.x * 8;
    const int tid = threadIdx.x;
    const int tlo = blockIdx.y * TCHUNK;
    const int thi = tlo + TCHUNK;
    float acc[8] = {0.f, 0.f, 0.f, 0.f, 0.f, 0.f, 0.f, 0.f};

    for (int t = tlo + tid * 4; t < thi; t += NTHR * 4) {
        float4 c = *(const float4*)&g_c3[t];
        const float* base = g_L3 + (size_t)b0 * TTP + t;
        #pragma unroll
        for (int j = 0; j < 8; j++) {
            float4 x = *(const float4*)(base + (size_t)j * TTP);
            acc[j] += c.x * x.x + c.y * x.y + c.z * x.z + c.w * x.w;
        }
    }
    if (blockIdx.y == 0) {
        for (int p = tid * 4; p < PPP; p += NTHR * 4) {
            float4 c = *(const float4*)&g_c2[p];
            const float* base = g_L2 + b0 * PPP + p;
            #pragma unroll
            for (int j = 0; j < 8; j++) {
                float4 x = *(const float4*)(base + j * PPP);
                acc[j] += c.x * x.x + c.y * x.y + c.z * x.z + c.w * x.w;
            }
        }
    }

    __shared__ float red[8][8];   // [warp][j]
    #pragma unroll
    for (int j = 0; j < 8; j++) {
        float vsum = acc[j];
        #pragma unroll
        for (int o = 16; o; o >>= 1) vsum += __shfl_down_sync(0xffffffffu, vsum, o);
        if ((tid & 31) == 0) red[tid >> 5][j] = vsum;
    }
    __syncthreads();
    if (tid < 8) {
        float s = 0.f;
        #pragma unroll
        for (int wp = 0; wp < 8; wp++) s += red[wp][tid];
        atomicAdd(&g_facc[b0 + tid], s);
    }
}

// ---------------------------------------------------------------------------
// Kernel E: epilogue -> logits
// ---------------------------------------------------------------------------
__global__ void epilogue(const float* __restrict__ bias, float* __restrict__ out)
{
    int b = blockIdx.x * blockDim.x + threadIdx.x;
    if (b < BB) out[b] = g_facc[b] + g_lin[b] + bias[0] + g_sumo;
}

// ---------------------------------------------------------------------------
extern "C" void kernel_launch(void* const* d_in, const int* in_sizes, int n_in,
                              void* d_out, int out_size)
{
    const int*   feats  = (const int*)  d_in[0];
    const float* w      = (const float*)d_in[1];
    const float* v      = (const float*)d_in[2];
    const float* bias   = (const float*)d_in[3];
    const float* gamma2 = (const float*)d_in[4];
    const float* beta2  = (const float*)d_in[5];
    const float* gw2    = (const float*)d_in[6];
    const float* gamma3 = (const float*)d_in[7];
    const float* beta3  = (const float*)d_in[8];
    const float* gw3    = (const float*)d_in[9];
    const int*   rows   = (const int*)  d_in[10];
    const int*   cols   = (const int*)  d_in[11];
    const int*   i1     = (const int*)  d_in[12];
    const int*   i2     = (const int*)  d_in[13];
    const int*   i3     = (const int*)  d_in[14];
    float* out = (float*)d_out;

    const int dyn_smem = (PP * SP + FF * SE) * (int)sizeof(float);  // 62.4 KB
    cudaFuncSetAttribute(compute_levels,
                         cudaFuncAttributeMaxDynamicSharedMemorySize, dyn_smem);

    pack_tri<<<TTP / NTHR, NTHR>>>(i1, i2, i3);
    compute_levels<<<BB, NTHR, dyn_smem>>>(feats, w, v, rows, cols);
    stats2_acc<<<dim3(PPP / 128, BSPLIT), NTHR>>>();
    stats3_acc<<<dim3(TTP / 128, BSPLIT), NTHR>>>();
    finalize<<<TTP / NTHR, NTHR>>>(gamma2, beta2, gw2, gamma3, beta3, gw3);
    final_reduce<<<dim3(BB / 8, TSPLIT), NTHR>>>();
    epilogue<<<BB / NTHR, NTHR>>>(bias, out);
}

// round 8
// speedup vs baseline: 1.9026x; 1.4967x over previous
#include <cuda_runtime.h>

#define BB   1024
#define FF   39
#define KK   16
#define PP   741
#define PPP  768                      // padded L2 row stride
#define TT   9139
#define TTP  9216                     // padded L3 row stride
#define SE   20                       // embedding row stride (floats)
#define NTHR 256
#define BSPLIT 16                     // batch split for stats kernels
#define TSPLIT 8                      // T split for final reduce
#define TCHUNK (TTP / TSPLIT)         // 1152

// ---- device-global scratch (no allocations allowed) ----
__device__ __align__(16) float g_L2[BB * PPP];          // ~3.1 MB (canonical q order)
__device__ __align__(16) float g_L3[(size_t)BB * TTP];  // ~37.7 MB (canonical tc order)
__device__ float g_lin[BB];
__device__ __align__(16) float g_c2[PPP];   // padding stays 0 (never written)
__device__ __align__(16) float g_c3[TTP];   // padding stays 0 (never written)
__device__ float g_s2[PPP], g_q2[PPP];
__device__ float g_s3[TTP], g_q3[TTP];
__device__ int   g_qdec[PP];                // a | (b2<<8), canonical pair order
__device__ float g_g2[PP], g_b2p[PP], g_w2[PP];   // BN params permuted to canonical
__device__ float g_g3[TT], g_b3p[TT], g_w3[TT];
__device__ float g_sumo;
__device__ float g_facc[BB];

// ---------------------------------------------------------------------------
// Kernel 0: build canonical orderings + permuted BN params; zero accumulators
//   pair  (a,b2):       q  = b2(b2-1)/2 + a                (b2-major)
//   triple(a,b2,c):     tc = c(c-1)(c-2)/6 + q
// ---------------------------------------------------------------------------
__global__ void pack_tri(const int* __restrict__ i1, const int* __restrict__ i2,
                         const int* __restrict__ i3,
                         const int* __restrict__ rows, const int* __restrict__ cols,
                         const float* __restrict__ gamma2, const float* __restrict__ beta2,
                         const float* __restrict__ gw2,
                         const float* __restrict__ gamma3, const float* __restrict__ beta3,
                         const float* __restrict__ gw3) {
    int t = blockIdx.x * blockDim.x + threadIdx.x;
    if (t < TT) {
        int a = i1[t], b2 = i2[t], c = i3[t];
        int tc = (c * (c - 1) * (c - 2)) / 6 + (b2 * (b2 - 1)) / 2 + a;
        g_g3[tc]  = gamma3[t];
        g_b3p[tc] = beta3[t];
        g_w3[tc]  = gw3[t];
    }
    if (t < PP) {
        int r = rows[t], cl = cols[t];            // r > cl
        int q = (r * (r - 1)) / 2 + cl;
        g_qdec[q] = cl | (r << 8);
        g_g2[q]  = gamma2[t];
        g_b2p[q] = beta2[t];
        g_w2[q]  = gw2[t];
    }
    if (t < TTP) { g_s3[t] = 0.f; g_q3[t] = 0.f; }
    if (t < PPP) { g_s2[t] = 0.f; g_q2[t] = 0.f; }
    if (t < BB)  g_facc[t] = 0.f;
    if (t == 0)  g_sumo = 0.f;
}

// ---------------------------------------------------------------------------
// Kernel A: per-batch-row gather + level2 + level3.
// Pair product lives in REGISTERS; third-factor Ec loads are warp-broadcast
// (adjacent q share b2 -> lanes loop over the same c). Crossbar traffic ~16x
// lower than smem-P2 variant; kernel is issue-bound, smem ~3 KB.
// ---------------------------------------------------------------------------
__global__ __launch_bounds__(NTHR) void compute_levels(
    const int*   __restrict__ feats,
    const float* __restrict__ w,
    const float* __restrict__ v)
{
    __shared__ float sxv[FF * SE];
    __shared__ int   sidx[FF];

    const int b   = blockIdx.x;
    const int tid = threadIdx.x;

    if (tid < FF) sidx[tid] = feats[b * FF + tid];
    __syncthreads();

    for (int e = tid; e < FF * KK; e += NTHR) {
        int f = e >> 4, k = e & 15;
        sxv[f * SE + k] = v[(size_t)sidx[f] * KK + k];
    }
    if (tid < 32) {
        float s = 0.f;
        for (int f = tid; f < FF; f += 32) s += w[sidx[f]];
        #pragma unroll
        for (int o = 16; o; o >>= 1) s += __shfl_down_sync(0xffffffffu, s, o);
        if (tid == 0) g_lin[b] = s;
    }
    __syncthreads();

    float* dstL3 = g_L3 + (size_t)b * TTP;

    for (int q = tid; q < PP; q += NTHR) {
        int d  = __ldg(&g_qdec[q]);
        int a  = d & 255, b2 = d >> 8;
        const float4* ea = (const float4*)&sxv[a * SE];
        const float4* eb = (const float4*)&sxv[b2 * SE];

        // pair product in registers + level2
        float4 p0, p1, p2, p3;
        {
            float4 x, y;
            x = ea[0]; y = eb[0];
            p0.x = x.x*y.x; p0.y = x.y*y.y; p0.z = x.z*y.z; p0.w = x.w*y.w;
            x = ea[1]; y = eb[1];
            p1.x = x.x*y.x; p1.y = x.y*y.y; p1.z = x.z*y.z; p1.w = x.w*y.w;
            x = ea[2]; y = eb[2];
            p2.x = x.x*y.x; p2.y = x.y*y.y; p2.z = x.z*y.z; p2.w = x.w*y.w;
            x = ea[3]; y = eb[3];
            p3.x = x.x*y.x; p3.y = x.y*y.y; p3.z = x.z*y.z; p3.w = x.w*y.w;
        }
        g_L2[b * PPP + q] = (p0.x+p0.y+p0.z+p0.w) + (p1.x+p1.y+p1.z+p1.w)
                          + (p2.x+p2.y+p2.z+p2.w) + (p3.x+p3.y+p3.z+p3.w);

        // c loop: base = C(c,3) tracked incrementally; store L3[base + q]
        int c0   = b2 + 1;
        int base = (c0 * (c0 - 1) * (c0 - 2)) / 6;
        int inc  = (c0 * (c0 - 1)) / 2;
        for (int c = c0; c < FF; c++) {
            const float4* ec = (const float4*)&sxv[c * SE];   // broadcast
            float4 e0 = ec[0], e1 = ec[1], e2 = ec[2], e3 = ec[3];
            float s0 = p0.x*e0.x + p0.y*e0.y + p0.z*e0.z + p0.w*e0.w;
            float s1 = p1.x*e1.x + p1.y*e1.y + p1.z*e1.z + p1.w*e1.w;
            float s2 = p2.x*e2.x + p2.y*e2.y + p2.z*e2.z + p2.w*e2.w;
            float s3 = p3.x*e3.x + p3.y*e3.y + p3.z*e3.z + p3.w*e3.w;
            dstL3[base + q] = (s0 + s1) + (s2 + s3);
            base += inc;
            inc  += c;
        }
    }
}

// ---------------------------------------------------------------------------
// Kernel B: batch-split column stats; partials via RED into g_s/g_q
// ---------------------------------------------------------------------------
__global__ __launch_bounds__(NTHR) void stats3_acc()
{
    __shared__ float4 ss[NTHR], sq[NTHR];
    const int tx = threadIdx.x & 31;
    const int ty = threadIdx.x >> 5;
    const int t0 = blockIdx.x * 128 + tx * 4;
    const int b0 = blockIdx.y * (BB / BSPLIT);

    float4 s = make_float4(0.f, 0.f, 0.f, 0.f);
    float4 q = make_float4(0.f, 0.f, 0.f, 0.f);
    #pragma unroll 8
    for (int i = ty; i < BB / BSPLIT; i += 8) {
        float4 x = *(const float4*)(g_L3 + (size_t)(b0 + i) * TTP + t0);
        s.x += x.x; s.y += x.y; s.z += x.z; s.w += x.w;
        q.x += x.x * x.x; q.y += x.y * x.y; q.z += x.z * x.z; q.w += x.w * x.w;
    }
    ss[threadIdx.x] = s; sq[threadIdx.x] = q;
    __syncthreads();
    if (ty == 0) {
        #pragma unroll
        for (int j = 1; j < 8; j++) {
            float4 a = ss[j * 32 + tx], c4 = sq[j * 32 + tx];
            s.x += a.x; s.y += a.y; s.z += a.z; s.w += a.w;
            q.x += c4.x; q.y += c4.y; q.z += c4.z; q.w += c4.w;
        }
        atomicAdd(&g_s3[t0 + 0], s.x); atomicAdd(&g_q3[t0 + 0], q.x);
        atomicAdd(&g_s3[t0 + 1], s.y); atomicAdd(&g_q3[t0 + 1], q.y);
        atomicAdd(&g_s3[t0 + 2], s.z); atomicAdd(&g_q3[t0 + 2], q.z);
        atomicAdd(&g_s3[t0 + 3], s.w); atomicAdd(&g_q3[t0 + 3], q.w);
    }
}

__global__ __launch_bounds__(NTHR) void stats2_acc()
{
    __shared__ float4 ss[NTHR], sq[NTHR];
    const int tx = threadIdx.x & 31;
    const int ty = threadIdx.x >> 5;
    const int p0 = blockIdx.x * 128 + tx * 4;
    const int b0 = blockIdx.y * (BB / BSPLIT);

    float4 s = make_float4(0.f, 0.f, 0.f, 0.f);
    float4 q = make_float4(0.f, 0.f, 0.f, 0.f);
    #pragma unroll 8
    for (int i = ty; i < BB / BSPLIT; i += 8) {
        float4 x = *(const float4*)(g_L2 + (b0 + i) * PPP + p0);
        s.x += x.x; s.y += x.y; s.z += x.z; s.w += x.w;
        q.x += x.x * x.x; q.y += x.y * x.y; q.z += x.z * x.z; q.w += x.w * x.w;
    }
    ss[threadIdx.x] = s; sq[threadIdx.x] = q;
    __syncthreads();
    if (ty == 0) {
        #pragma unroll
        for (int j = 1; j < 8; j++) {
            float4 a = ss[j * 32 + tx], c4 = sq[j * 32 + tx];
            s.x += a.x; s.y += a.y; s.z += a.z; s.w += a.w;
            q.x += c4.x; q.y += c4.y; q.z += c4.z; q.w += c4.w;
        }
        atomicAdd(&g_s2[p0 + 0], s.x); atomicAdd(&g_q2[p0 + 0], q.x);
        atomicAdd(&g_s2[p0 + 1], s.y); atomicAdd(&g_q2[p0 + 1], q.y);
        atomicAdd(&g_s2[p0 + 2], s.z); atomicAdd(&g_q2[p0 + 2], q.z);
        atomicAdd(&g_s2[p0 + 3], s.w); atomicAdd(&g_q2[p0 + 3], q.w);
    }
}

// ---------------------------------------------------------------------------
// Kernel C: sums -> affine coefficients c (canonical order, permuted params)
// ---------------------------------------------------------------------------
__global__ __launch_bounds__(NTHR) void finalize()
{
    const int i = blockIdx.x * NTHR + threadIdx.x;
    float osum = 0.f;
    if (i < TT) {
        float mean = g_s3[i] * (1.0f / BB);
        float var  = g_q3[i] * (1.0f / BB) - mean * mean;
        float inv  = rsqrtf(var + 1e-3f);
        float cc   = g_g3[i] * g_w3[i] * inv;
        g_c3[i] = cc;
        osum += g_b3p[i] * g_w3[i] - cc * mean;
    }
    if (i < PP) {
        float mean = g_s2[i] * (1.0f / BB);
        float var  = g_q2[i] * (1.0f / BB) - mean * mean;
        float inv  = rsqrtf(var + 1e-3f);
        float cc   = g_g2[i] * g_w2[i] * inv;
        g_c2[i] = cc;
        osum += g_b2p[i] * g_w2[i] - cc * mean;
    }
    #pragma unroll
    for (int o = 16; o; o >>= 1) osum += __shfl_down_sync(0xffffffffu, osum, o);
    __shared__ float red[8];
    if ((threadIdx.x & 31) == 0) red[threadIdx.x >> 5] = osum;
    __syncthreads();
    if (threadIdx.x == 0) {
        float s = 0.f;
        #pragma unroll
        for (int j = 0; j < 8; j++) s += red[j];
        atomicAdd(&g_sumo, s);
    }
}

// ---------------------------------------------------------------------------
// Kernel D: weighted reductions. 8 b-rows per CTA, T split 8-way (grid.y).
// Padding columns carry c3=0 so the loop is guard-free and fully float4.
// ---------------------------------------------------------------------------
__global__ __launch_bounds__(NTHR) void final_reduce()
{
    const int b0  = blockIdx.x * 8;
    const int tid = threadIdx.x;
    const int tlo = blockIdx.y * TCHUNK;
    const int thi = tlo + TCHUNK;
    float acc[8] = {0.f, 0.f, 0.f, 0.f, 0.f, 0.f, 0.f, 0.f};

    for (int t = tlo + tid * 4; t < thi; t += NTHR * 4) {
        float4 c = *(const float4*)&g_c3[t];
        const float* base = g_L3 + (size_t)b0 * TTP + t;
        #pragma unroll
        for (int j = 0; j < 8; j++) {
            float4 x = *(const float4*)(base + (size_t)j * TTP);
            acc[j] += c.x * x.x + c.y * x.y + c.z * x.z + c.w * x.w;
        }
    }
    if (blockIdx.y == 0) {
        for (int p = tid * 4; p < PPP; p += NTHR * 4) {
            float4 c = *(const float4*)&g_c2[p];
            const float* base = g_L2 + b0 * PPP + p;
            #pragma unroll
            for (int j = 0; j < 8; j++) {
                float4 x = *(const float4*)(base + j * PPP);
                acc[j] += c.x * x.x + c.y * x.y + c.z * x.z + c.w * x.w;
            }
        }
    }

    __shared__ float red[8][8];   // [warp][j]
    #pragma unroll
    for (int j = 0; j < 8; j++) {
        float vsum = acc[j];
        #pragma unroll
        for (int o = 16; o; o >>= 1) vsum += __shfl_down_sync(0xffffffffu, vsum, o);
        if ((tid & 31) == 0) red[tid >> 5][j] = vsum;
    }
    __syncthreads();
    if (tid < 8) {
        float s = 0.f;
        #pragma unroll
        for (int wp = 0; wp < 8; wp++) s += red[wp][tid];
        atomicAdd(&g_facc[b0 + tid], s);
    }
}

// ---------------------------------------------------------------------------
// Kernel E: epilogue -> logits
// ---------------------------------------------------------------------------
__global__ void epilogue(const float* __restrict__ bias, float* __restrict__ out)
{
    int b = blockIdx.x * blockDim.x + threadIdx.x;
    if (b < BB) out[b] = g_facc[b] + g_lin[b] + bias[0] + g_sumo;
}

// ---------------------------------------------------------------------------
extern "C" void kernel_launch(void* const* d_in, const int* in_sizes, int n_in,
                              void* d_out, int out_size)
{
    const int*   feats  = (const int*)  d_in[0];
    const float* w      = (const float*)d_in[1];
    const float* v      = (const float*)d_in[2];
    const float* bias   = (const float*)d_in[3];
    const float* gamma2 = (const float*)d_in[4];
    const float* beta2  = (const float*)d_in[5];
    const float* gw2    = (const float*)d_in[6];
    const float* gamma3 = (const float*)d_in[7];
    const float* beta3  = (const float*)d_in[8];
    const float* gw3    = (const float*)d_in[9];
    const int*   rows   = (const int*)  d_in[10];
    const int*   cols   = (const int*)  d_in[11];
    const int*   i1     = (const int*)  d_in[12];
    const int*   i2     = (const int*)  d_in[13];
    const int*   i3     = (const int*)  d_in[14];
    float* out = (float*)d_out;

    pack_tri<<<TTP / NTHR, NTHR>>>(i1, i2, i3, rows, cols,
                                   gamma2, beta2, gw2, gamma3, beta3, gw3);
    compute_levels<<<BB, NTHR>>>(feats, w, v);
    stats2_acc<<<dim3(PPP / 128, BSPLIT), NTHR>>>();
    stats3_acc<<<dim3(TTP / 128, BSPLIT), NTHR>>>();
    finalize<<<TTP / NTHR, NTHR>>>();
    final_reduce<<<dim3(BB / 8, TSPLIT), NTHR>>>();
    epilogue<<<BB / NTHR, NTHR>>>(bias, out);
}